// round 7
// baseline (speedup 1.0000x reference)
#include <cuda_runtime.h>
#include <cuda_bf16.h>
#include <cstdint>

#define DD   128
#define EB   128
#define NTHR 256
#define MAXN 100000

// ---- dynamic smem layout (bytes) ------------------------------------------
// GEMM phases:  W buf0 @0, W buf1 @34816 (each hi 17408 + lo 17408)
//               A hi @69632 (128 x 72 bf16), A lo @88064
// hidden phase: H hi @69632 (128 x 136 bf16), H lo @0 (W buf0 region)
// epilogue:     Hs fp32 (128 x 132) @0
#define OFF_WB0  0
#define W_LO     17408
#define OFF_WB1  34816
#define OFF_AH   69632
#define OFF_AL   88064
#define OFF_TAIL 106496
// tail: +0 sIdx(256 int)/csum(129 f) | +1024 muS | +1536 invS
//       +2048 b1S | +2560 b2S | +3072 gmaS | +3584 btaS
#define SMEM_BYTES 110592

// ---- device global scratch ------------------------------------------------
__device__ float g_agg[(size_t)MAXN * DD];
__device__ float g_colsum[DD];
__device__ float g_sumsq[1];
__device__ float g_mean[DD];
__device__ float g_invrms[1];
__device__ __nv_bfloat16 g_xh[(size_t)MAXN * DD];
__device__ __nv_bfloat16 g_xl[(size_t)MAXN * DD];
__device__ __nv_bfloat16 g_eW1h[3 * DD * DD], g_eW1l[3 * DD * DD];
__device__ __nv_bfloat16 g_eW2h[DD * DD],     g_eW2l[DD * DD];
__device__ __nv_bfloat16 g_nW1h[2 * DD * DD], g_nW1l[2 * DD * DD];
__device__ __nv_bfloat16 g_nW2h[DD * DD],     g_nW2l[DD * DD];

// ---- helpers --------------------------------------------------------------
static __device__ __forceinline__ void warp_red2(float& a, float& b) {
#pragma unroll
    for (int o = 16; o > 0; o >>= 1) {
        a += __shfl_xor_sync(0xffffffffu, a, o);
        b += __shfl_xor_sync(0xffffffffu, b, o);
    }
}
static __device__ __forceinline__ void ldsm4(unsigned r[4], unsigned addr) {
    asm volatile("ldmatrix.sync.aligned.m8n8.x4.shared.b16 {%0,%1,%2,%3}, [%4];\n"
                 : "=r"(r[0]), "=r"(r[1]), "=r"(r[2]), "=r"(r[3]) : "r"(addr));
}
static __device__ __forceinline__ void ldsm4t(unsigned r[4], unsigned addr) {
    asm volatile("ldmatrix.sync.aligned.m8n8.x4.trans.shared.b16 {%0,%1,%2,%3}, [%4];\n"
                 : "=r"(r[0]), "=r"(r[1]), "=r"(r[2]), "=r"(r[3]) : "r"(addr));
}
static __device__ __forceinline__ void mma16816(float d[4], const unsigned a[4],
                                                unsigned b0, unsigned b1) {
    asm volatile("mma.sync.aligned.m16n8k16.row.col.f32.bf16.bf16.f32 "
                 "{%0,%1,%2,%3}, {%4,%5,%6,%7}, {%8,%9}, {%0,%1,%2,%3};\n"
                 : "+f"(d[0]), "+f"(d[1]), "+f"(d[2]), "+f"(d[3])
                 : "r"(a[0]), "r"(a[1]), "r"(a[2]), "r"(a[3]), "r"(b0), "r"(b1));
}
static __device__ __forceinline__ void cp16(unsigned saddr, const void* g) {
    asm volatile("cp.async.cg.shared.global [%0], [%1], 16;\n" :: "r"(saddr), "l"(g));
}
static __device__ __forceinline__ void cp_commit() { asm volatile("cp.async.commit_group;\n"); }
static __device__ __forceinline__ void cp_wait0()  { asm volatile("cp.async.wait_group 0;\n" ::: "memory"); }
static __device__ __forceinline__ void red4(float* p, float4 v) {
    asm volatile("red.global.add.v4.f32 [%0], {%1,%2,%3,%4};\n"
                 :: "l"(p), "f"(v.x), "f"(v.y), "f"(v.z), "f"(v.w) : "memory");
}
static __device__ __forceinline__ void split2(float a, float b, uint32_t& hi, uint32_t& lo) {
    __nv_bfloat162 h = __floats2bfloat162_rn(a, b);
    __nv_bfloat162 l = __floats2bfloat162_rn(a - __bfloat162float(h.x), b - __bfloat162float(h.y));
    hi = *(uint32_t*)&h;
    lo = *(uint32_t*)&l;
}
template <int STR>
static __device__ __forceinline__ void split_store_s(__nv_bfloat16* H, __nv_bfloat16* L,
                                                     int r, int c, float4 v) {
    uint32_t h01, l01, h23, l23;
    split2(v.x, v.y, h01, l01);
    split2(v.z, v.w, h23, l23);
    *(uint32_t*)(H + r * STR + c)     = h01;
    *(uint32_t*)(H + r * STR + c + 2) = h23;
    *(uint32_t*)(L + r * STR + c)     = l01;
    *(uint32_t*)(L + r * STR + c + 2) = l23;
}

// one K=64 chunk of 3-pass bf16-split MMA: acc += A(128x64) * W(64x128)
static __device__ __forceinline__ void mma_chunk64(float acc[2][8][4],
                                                   unsigned ahB, unsigned alB,
                                                   int astr, int acol0,
                                                   unsigned whB, unsigned wlB,
                                                   int wm, int wn, int lane) {
    const int ar  = lane & 15;
    const int asl = (lane >> 4) * 8;
#pragma unroll
    for (int ks = 0; ks < 4; ks++) {
        unsigned a_h[2][4], a_l[2][4];
        const int acol = acol0 + ks * 16 + asl;
#pragma unroll
        for (int mt = 0; mt < 2; mt++) {
            int arow = wm * 32 + mt * 16 + ar;
            unsigned off = (unsigned)((arow * astr + acol) * 2);
            ldsm4(a_h[mt], ahB + off);
            ldsm4(a_l[mt], alB + off);
        }
        const int brow = ks * 16 + ar;
#pragma unroll
        for (int np = 0; np < 4; np++) {
            int bcol = wn * 64 + np * 16 + asl;
            unsigned off = (unsigned)((brow * 136 + bcol) * 2);
            unsigned bh[4], bl[4];
            ldsm4t(bh, whB + off);
            ldsm4t(bl, wlB + off);
#pragma unroll
            for (int mt = 0; mt < 2; mt++) {
                mma16816(acc[mt][2 * np],     a_h[mt], bh[0], bh[1]);
                mma16816(acc[mt][2 * np],     a_h[mt], bl[0], bl[1]);
                mma16816(acc[mt][2 * np],     a_l[mt], bh[0], bh[1]);
                mma16816(acc[mt][2 * np + 1], a_h[mt], bh[2], bh[3]);
                mma16816(acc[mt][2 * np + 1], a_h[mt], bl[2], bl[3]);
                mma16816(acc[mt][2 * np + 1], a_l[mt], bh[2], bh[3]);
            }
        }
    }
}

// issue cp.async for one 64x128 weight chunk (hi+lo) into W buffer at wbase
static __device__ __forceinline__ void load_w64(unsigned wbase,
                                                const __nv_bfloat16* Wh,
                                                const __nv_bfloat16* Wl, int tid) {
#pragma unroll
    for (int i = 0; i < 4; i++) {
        int idx = tid + NTHR * i;
        int r = idx >> 4, u = (idx & 15) * 8;
        unsigned so = (unsigned)((r * 136 + u) * 2);
        cp16(wbase + so,        Wh + r * DD + u);
        cp16(wbase + W_LO + so, Wl + r * DD + u);
    }
}

// hidden: bias+relu, split -> Hh (stride 136) / Hl; zero acc
static __device__ __forceinline__ void hidden_split(float acc[2][8][4],
                                                    __nv_bfloat16* Hh, __nv_bfloat16* Hl,
                                                    const float* b1S, int wm, int wn, int lane) {
    const int g = lane >> 2, t = lane & 3;
#pragma unroll
    for (int mt = 0; mt < 2; mt++) {
#pragma unroll
        for (int nt = 0; nt < 8; nt++) {
            int col = wn * 64 + nt * 8 + t * 2;
            float bx = b1S[col], by = b1S[col + 1];
            int r0 = wm * 32 + mt * 16 + g;
            float h0 = fmaxf(acc[mt][nt][0] + bx, 0.f);
            float h1 = fmaxf(acc[mt][nt][1] + by, 0.f);
            float h2 = fmaxf(acc[mt][nt][2] + bx, 0.f);
            float h3 = fmaxf(acc[mt][nt][3] + by, 0.f);
            uint32_t hi, lo;
            split2(h0, h1, hi, lo);
            *(uint32_t*)(Hh + r0 * 136 + col) = hi;
            *(uint32_t*)(Hl + r0 * 136 + col) = lo;
            split2(h2, h3, hi, lo);
            *(uint32_t*)(Hh + (r0 + 8) * 136 + col) = hi;
            *(uint32_t*)(Hl + (r0 + 8) * 136 + col) = lo;
            acc[mt][nt][0] = acc[mt][nt][1] = acc[mt][nt][2] = acc[mt][nt][3] = 0.f;
        }
    }
}

// acc + b2 -> Hs fp32 (stride 132)
static __device__ __forceinline__ void out_store(const float acc[2][8][4], float* Hs,
                                                 const float* b2S, int wm, int wn, int lane) {
    const int g = lane >> 2, t = lane & 3;
#pragma unroll
    for (int mt = 0; mt < 2; mt++) {
#pragma unroll
        for (int nt = 0; nt < 8; nt++) {
            int col = wn * 64 + nt * 8 + t * 2;
            float bx = b2S[col], by = b2S[col + 1];
            int r0 = wm * 32 + mt * 16 + g;
            *(float2*)(Hs + r0 * 132 + col)       = make_float2(acc[mt][nt][0] + bx, acc[mt][nt][1] + by);
            *(float2*)(Hs + (r0 + 8) * 132 + col) = make_float2(acc[mt][nt][2] + bx, acc[mt][nt][3] + by);
        }
    }
}

// per-row LN stats from Hs -> muS/invS
static __device__ __forceinline__ void stats_rows(const float* Hs, float* muS, float* invS,
                                                  int wid, int lane) {
#pragma unroll 1
    for (int j = 0; j < 16; j++) {
        int r = wid * 16 + j;
        float s = 0.f, sq = 0.f;
#pragma unroll
        for (int q = 0; q < 4; q++) {
            float v = Hs[r * 132 + lane + 32 * q];
            s += v; sq += v * v;
        }
        warp_red2(s, sq);
        if (lane == 0) {
            float mu = s * (1.f / 128.f);
            muS[r]  = mu;
            invS[r] = rsqrtf(sq * (1.f / 128.f) - mu * mu + 1e-5f);
        }
    }
}

// ---- prep kernels ---------------------------------------------------------
__global__ void prep_split(const float* __restrict__ src, __nv_bfloat16* __restrict__ h,
                           __nv_bfloat16* __restrict__ l, int n4) {
    int i = blockIdx.x * blockDim.x + threadIdx.x;
    if (i >= n4) return;
    float4 v = ((const float4*)src)[i];
    uint32_t h01, l01, h23, l23;
    split2(v.x, v.y, h01, l01);
    split2(v.z, v.w, h23, l23);
    ((uint32_t*)h)[2 * i] = h01; ((uint32_t*)h)[2 * i + 1] = h23;
    ((uint32_t*)l)[2 * i] = l01; ((uint32_t*)l)[2 * i + 1] = l23;
}

// ---------------------------------------------------------------------------
__global__ void __launch_bounds__(NTHR, 2)
edge_kernel(const float* __restrict__ ea,
            const int* __restrict__ ei,
            const float* __restrict__ b1, const float* __restrict__ b2,
            const float* __restrict__ gma, const float* __restrict__ bta,
            float* __restrict__ eout, int E)
{
    extern __shared__ char smc[];
    const unsigned sbase = (unsigned)__cvta_generic_to_shared(smc);
    int*   sIdx = (int*)(smc + OFF_TAIL);
    float* muS  = (float*)(smc + OFF_TAIL + 1024);
    float* invS = (float*)(smc + OFF_TAIL + 1536);
    float* b1S  = (float*)(smc + OFF_TAIL + 2048);
    float* b2S  = (float*)(smc + OFF_TAIL + 2560);
    float* gmaS = (float*)(smc + OFF_TAIL + 3072);
    float* btaS = (float*)(smc + OFF_TAIL + 3584);
    float* Hs   = (float*)smc;

    const int tid = threadIdx.x, lane = tid & 31, wid = tid >> 5;
    const int wm = wid & 3, wn = wid >> 2;
    const int eb = blockIdx.x * EB;
    const int Eloc = min(EB, E - eb);

    if (tid < 128) {
        sIdx[tid] = (tid < Eloc) ? ei[eb + tid] : 0;
        b1S[tid] = b1[tid]; b2S[tid] = b2[tid];
        gmaS[tid] = gma[tid]; btaS[tid] = bta[tid];
    } else {
        int t2 = tid - 128;
        sIdx[tid] = (t2 < Eloc) ? ei[E + eb + t2] : 0;
    }
    __syncthreads();

    // A chunk loader (chunk 0..5)
    auto loadA = [&](int chunk) {
        if (chunk < 4) {
            const int seg = chunk >> 1, c0 = (chunk & 1) * 64;
#pragma unroll
            for (int i = 0; i < 4; i++) {
                int idx = tid + NTHR * i;
                int r = idx >> 3, u = (idx & 7) * 8;
                size_t grow = (size_t)sIdx[seg * 128 + r] * DD + c0 + u;
                unsigned so = (unsigned)((r * 72 + u) * 2);
                cp16(sbase + OFF_AH + so, g_xh + grow);
                cp16(sbase + OFF_AL + so, g_xl + grow);
            }
        } else {
            const int c0 = (chunk - 4) * 64;
            __nv_bfloat16* Ah = (__nv_bfloat16*)(smc + OFF_AH);
            __nv_bfloat16* Al = (__nv_bfloat16*)(smc + OFF_AL);
#pragma unroll
            for (int i = 0; i < 8; i++) {
                int idx = tid + NTHR * i;
                int r = idx >> 4, c4 = (idx & 15) * 4;
                if (r < Eloc) {
                    float4 v = *(const float4*)(ea + (size_t)(eb + r) * DD + c0 + c4);
                    split_store_s<72>(Ah, Al, r, c4, v);
                }
            }
        }
    };

    float acc[2][8][4];
#pragma unroll
    for (int mt = 0; mt < 2; mt++)
#pragma unroll
        for (int nt = 0; nt < 8; nt++)
#pragma unroll
            for (int q = 0; q < 4; q++) acc[mt][nt][q] = 0.f;

    // prologue: W0 -> buf0, A0
    load_w64(sbase + OFF_WB0, g_eW1h, g_eW1l, tid);
    loadA(0);
    cp_commit(); cp_wait0();
    __syncthreads();

    // ---- GEMM1: 6 chunks, W double-buffered ----
#pragma unroll 1
    for (int c = 0; c < 6; c++) {
        if (c < 5) {  // prefetch next W into other buffer (overlaps MMA)
            unsigned wb = ((c + 1) & 1) ? OFF_WB1 : OFF_WB0;
            load_w64(sbase + wb, g_eW1h + (c + 1) * 64 * DD, g_eW1l + (c + 1) * 64 * DD, tid);
            cp_commit();
        }
        unsigned wb = (c & 1) ? OFF_WB1 : OFF_WB0;
        mma_chunk64(acc, sbase + OFF_AH, sbase + OFF_AL, 72, 0,
                    sbase + wb, sbase + wb + W_LO, wm, wn, lane);
        __syncthreads();               // A consumed by all warps
        if (c < 5) {
            loadA(c + 1);
            cp_commit(); cp_wait0();   // A(c+1) + W(c+1) ready
            __syncthreads();
        }
    }

    // ---- hidden: prefetch GEMM2 W0 -> buf1, then split acc ----
    load_w64(sbase + OFF_WB1, g_eW2h, g_eW2l, tid);
    cp_commit();
    hidden_split(acc, (__nv_bfloat16*)(smc + OFF_AH), (__nv_bfloat16*)(smc + OFF_WB0),
                 b1S, wm, wn, lane);
    cp_wait0();
    __syncthreads();

    // ---- GEMM2: 2 chunks ----
    mma_chunk64(acc, sbase + OFF_AH, sbase + OFF_WB0, 136, 0,
                sbase + OFF_WB1, sbase + OFF_WB1 + W_LO, wm, wn, lane);
    __syncthreads();
    load_w64(sbase + OFF_WB1, g_eW2h + 64 * DD, g_eW2l + 64 * DD, tid);
    cp_commit(); cp_wait0();
    __syncthreads();
    mma_chunk64(acc, sbase + OFF_AH, sbase + OFF_WB0, 136, 64,
                sbase + OFF_WB1, sbase + OFF_WB1 + W_LO, wm, wn, lane);
    __syncthreads();

    // ---- epilogue ----
    out_store(acc, Hs, b2S, wm, wn, lane);
    __syncthreads();
    stats_rows(Hs, muS, invS, wid, lane);
    __syncthreads();

    const int c4 = 4 * lane;
    float4 g4 = *(const float4*)(gmaS + c4);
    float4 t4 = *(const float4*)(btaS + c4);
#pragma unroll 1
    for (int j = 0; j < 16; j++) {
        int r = wid * 16 + j;                  // warp-uniform
        if (r >= Eloc) continue;
        size_t ge = (size_t)(eb + r);
        float mu = muS[r], inv = invS[r];
        float4 v = *(const float4*)(Hs + r * 132 + c4);
        float4 o;
        o.x = (v.x - mu) * inv * g4.x + t4.x;
        o.y = (v.y - mu) * inv * g4.y + t4.y;
        o.z = (v.z - mu) * inv * g4.z + t4.z;
        o.w = (v.w - mu) * inv * g4.w + t4.w;
        float4 e4 = *(const float4*)(ea + ge * DD + c4);
        e4.x += o.x; e4.y += o.y; e4.z += o.z; e4.w += o.w;
        *(float4*)(eout + ge * DD + c4) = e4;
        red4(&g_agg[(size_t)sIdx[128 + r] * DD + c4], o);
    }
}

// ---------------------------------------------------------------------------
__global__ void __launch_bounds__(NTHR, 2)
node_kernel(const float* __restrict__ x,
            const float* __restrict__ b1, const float* __restrict__ b2,
            const float* __restrict__ gma, const float* __restrict__ bta,
            float* __restrict__ xpre, int Nn)
{
    extern __shared__ char smc[];
    const unsigned sbase = (unsigned)__cvta_generic_to_shared(smc);
    float* csum_s = (float*)(smc + OFF_TAIL);
    float* muS  = (float*)(smc + OFF_TAIL + 1024);
    float* invS = (float*)(smc + OFF_TAIL + 1536);
    float* b1S  = (float*)(smc + OFF_TAIL + 2048);
    float* b2S  = (float*)(smc + OFF_TAIL + 2560);
    float* gmaS = (float*)(smc + OFF_TAIL + 3072);
    float* btaS = (float*)(smc + OFF_TAIL + 3584);
    float* Hs   = (float*)smc;

    const int tid = threadIdx.x, lane = tid & 31, wid = tid >> 5;
    const int wm = wid & 3, wn = wid >> 2;
    const int nb = blockIdx.x * EB;
    const int Nloc = min(EB, Nn - nb);

    if (tid < 128) {
        b1S[tid] = b1[tid]; b2S[tid] = b2[tid];
        gmaS[tid] = gma[tid]; btaS[tid] = bta[tid];
    }
    if (tid < 129) csum_s[tid] = 0.f;
    __syncthreads();

    auto loadA = [&](int chunk) {
        const int c0 = (chunk & 1) * 64;
        if (chunk < 2) {
#pragma unroll
            for (int i = 0; i < 4; i++) {
                int idx = tid + NTHR * i;
                int r = idx >> 3, u = (idx & 7) * 8;
                if (r < Nloc) {
                    size_t grow = (size_t)(nb + r) * DD + c0 + u;
                    unsigned so = (unsigned)((r * 72 + u) * 2);
                    cp16(sbase + OFF_AH + so, g_xh + grow);
                    cp16(sbase + OFF_AL + so, g_xl + grow);
                }
            }
        } else {
            __nv_bfloat16* Ah = (__nv_bfloat16*)(smc + OFF_AH);
            __nv_bfloat16* Al = (__nv_bfloat16*)(smc + OFF_AL);
#pragma unroll
            for (int i = 0; i < 8; i++) {
                int idx = tid + NTHR * i;
                int r = idx >> 4, c4 = (idx & 15) * 4;
                if (r < Nloc) {
                    float4 v = *(const float4*)(g_agg + (size_t)(nb + r) * DD + c0 + c4);
                    split_store_s<72>(Ah, Al, r, c4, v);
                }
            }
        }
    };

    float acc[2][8][4];
#pragma unroll
    for (int mt = 0; mt < 2; mt++)
#pragma unroll
        for (int nt = 0; nt < 8; nt++)
#pragma unroll
            for (int q = 0; q < 4; q++) acc[mt][nt][q] = 0.f;

    load_w64(sbase + OFF_WB0, g_nW1h, g_nW1l, tid);
    loadA(0);
    cp_commit(); cp_wait0();
    __syncthreads();

    // ---- GEMM1: 4 chunks ----
#pragma unroll 1
    for (int c = 0; c < 4; c++) {
        if (c < 3) {
            unsigned wb = ((c + 1) & 1) ? OFF_WB1 : OFF_WB0;
            load_w64(sbase + wb, g_nW1h + (c + 1) * 64 * DD, g_nW1l + (c + 1) * 64 * DD, tid);
            cp_commit();
        }
        unsigned wb = (c & 1) ? OFF_WB1 : OFF_WB0;
        mma_chunk64(acc, sbase + OFF_AH, sbase + OFF_AL, 72, 0,
                    sbase + wb, sbase + wb + W_LO, wm, wn, lane);
        __syncthreads();
        if (c < 3) {
            loadA(c + 1);
            cp_commit(); cp_wait0();
            __syncthreads();
        }
    }

    load_w64(sbase + OFF_WB1, g_nW2h, g_nW2l, tid);
    cp_commit();
    hidden_split(acc, (__nv_bfloat16*)(smc + OFF_AH), (__nv_bfloat16*)(smc + OFF_WB0),
                 b1S, wm, wn, lane);
    cp_wait0();
    __syncthreads();

    mma_chunk64(acc, sbase + OFF_AH, sbase + OFF_WB0, 136, 0,
                sbase + OFF_WB1, sbase + OFF_WB1 + W_LO, wm, wn, lane);
    __syncthreads();
    load_w64(sbase + OFF_WB1, g_nW2h + 64 * DD, g_nW2l + 64 * DD, tid);
    cp_commit(); cp_wait0();
    __syncthreads();
    mma_chunk64(acc, sbase + OFF_AH, sbase + OFF_WB0, 136, 64,
                sbase + OFF_WB1, sbase + OFF_WB1 + W_LO, wm, wn, lane);
    __syncthreads();

    out_store(acc, Hs, b2S, wm, wn, lane);
    __syncthreads();
    stats_rows(Hs, muS, invS, wid, lane);
    __syncthreads();

    // ---- LN + residual + PairNorm partials (float4 lanes) ----
    const int c4 = 4 * lane;
    float4 g4 = *(const float4*)(gmaS + c4);
    float4 t4 = *(const float4*)(btaS + c4);
    float4 cs = make_float4(0.f, 0.f, 0.f, 0.f);
    float sq_acc = 0.f;
#pragma unroll 1
    for (int j = 0; j < 16; j++) {
        int r = wid * 16 + j;
        if (r >= Nloc) continue;
        size_t gn = (size_t)(nb + r);
        float mu = muS[r], inv = invS[r];
        float4 v = *(const float4*)(Hs + r * 132 + c4);
        float4 xv = *(const float4*)(x + gn * DD + c4);
        float4 xp;
        xp.x = xv.x + (v.x - mu) * inv * g4.x + t4.x;
        xp.y = xv.y + (v.y - mu) * inv * g4.y + t4.y;
        xp.z = xv.z + (v.z - mu) * inv * g4.z + t4.z;
        xp.w = xv.w + (v.w - mu) * inv * g4.w + t4.w;
        *(float4*)(xpre + gn * DD + c4) = xp;
        cs.x += xp.x; cs.y += xp.y; cs.z += xp.z; cs.w += xp.w;
        sq_acc += xp.x * xp.x + xp.y * xp.y + xp.z * xp.z + xp.w * xp.w;
    }
    atomicAdd(&csum_s[c4 + 0], cs.x);
    atomicAdd(&csum_s[c4 + 1], cs.y);
    atomicAdd(&csum_s[c4 + 2], cs.z);
    atomicAdd(&csum_s[c4 + 3], cs.w);
#pragma unroll
    for (int o = 16; o > 0; o >>= 1) sq_acc += __shfl_xor_sync(0xffffffffu, sq_acc, o);
    if (lane == 0) atomicAdd(&csum_s[128], sq_acc);
    __syncthreads();
    if (tid < 128)       atomicAdd(&g_colsum[tid], csum_s[tid]);
    else if (tid == 128) atomicAdd(&g_sumsq[0],    csum_s[128]);
}

// ---------------------------------------------------------------------------
__global__ void rms_kernel(int Nn)
{
    __shared__ float red[128];
    int c = threadIdx.x;
    float m = g_colsum[c] / (float)Nn;
    g_mean[c] = m;
    red[c] = m * m;
    __syncthreads();
    for (int o = 64; o > 0; o >>= 1) {
        if (c < o) red[c] += red[c + o];
        __syncthreads();
    }
    if (c == 0) {
        float ssc = g_sumsq[0] - (float)Nn * red[0];
        float rms = sqrtf(ssc / (float)Nn) + 1e-8f;
        g_invrms[0] = 1.0f / rms;
    }
}

__global__ void finalize_kernel(float* __restrict__ xout, int n4)
{
    int i = blockIdx.x * blockDim.x + threadIdx.x;
    if (i < n4) {
        float4 v = ((const float4*)xout)[i];
        int c = (i * 4) & 127;
        float inv = g_invrms[0];
        v.x = (v.x - g_mean[c])     * inv;
        v.y = (v.y - g_mean[c + 1]) * inv;
        v.z = (v.z - g_mean[c + 2]) * inv;
        v.w = (v.w - g_mean[c + 3]) * inv;
        ((float4*)xout)[i] = v;
    }
}

// ---------------------------------------------------------------------------
extern "C" void kernel_launch(void* const* d_in, const int* in_sizes, int n_in,
                              void* d_out, int out_size)
{
    const float* x   = (const float*)d_in[0];
    const float* ea  = (const float*)d_in[1];
    const int*   ei  = (const int*)d_in[2];      // int32 (JAX x64 disabled)
    const float* eW1 = (const float*)d_in[3];
    const float* eb1 = (const float*)d_in[4];
    const float* eW2 = (const float*)d_in[5];
    const float* eb2 = (const float*)d_in[6];
    const float* eg  = (const float*)d_in[7];
    const float* ebt = (const float*)d_in[8];
    const float* nW1 = (const float*)d_in[9];
    const float* nb1 = (const float*)d_in[10];
    const float* nW2 = (const float*)d_in[11];
    const float* nb2 = (const float*)d_in[12];
    const float* ng  = (const float*)d_in[13];
    const float* nbt = (const float*)d_in[14];

    const int Nn = in_sizes[0] / DD;
    const int E  = in_sizes[1] / DD;

    float* xout = (float*)d_out;
    float* eout = xout + (size_t)Nn * DD;

    cudaFuncSetAttribute(edge_kernel, cudaFuncAttributeMaxDynamicSharedMemorySize, SMEM_BYTES);
    cudaFuncSetAttribute(node_kernel, cudaFuncAttributeMaxDynamicSharedMemorySize, SMEM_BYTES);

    void *aggp, *csp, *sqp, *xhp, *xlp;
    void *e1h, *e1l, *e2h, *e2l, *n1h, *n1l, *n2h, *n2l;
    cudaGetSymbolAddress(&aggp, g_agg);
    cudaGetSymbolAddress(&csp,  g_colsum);
    cudaGetSymbolAddress(&sqp,  g_sumsq);
    cudaGetSymbolAddress(&xhp,  g_xh);
    cudaGetSymbolAddress(&xlp,  g_xl);
    cudaGetSymbolAddress(&e1h, g_eW1h); cudaGetSymbolAddress(&e1l, g_eW1l);
    cudaGetSymbolAddress(&e2h, g_eW2h); cudaGetSymbolAddress(&e2l, g_eW2l);
    cudaGetSymbolAddress(&n1h, g_nW1h); cudaGetSymbolAddress(&n1l, g_nW1l);
    cudaGetSymbolAddress(&n2h, g_nW2h); cudaGetSymbolAddress(&n2l, g_nW2l);

    cudaMemsetAsync(aggp, 0, (size_t)Nn * DD * sizeof(float));
    cudaMemsetAsync(csp,  0, DD * sizeof(float));
    cudaMemsetAsync(sqp,  0, sizeof(float));

    {
        int n4 = Nn * DD / 4;
        prep_split<<<(n4 + 255) / 256, 256>>>(x, (__nv_bfloat16*)xhp, (__nv_bfloat16*)xlp, n4);
        int w1 = 3 * DD * DD / 4;
        prep_split<<<(w1 + 255) / 256, 256>>>(eW1, (__nv_bfloat16*)e1h, (__nv_bfloat16*)e1l, w1);
        int w2 = DD * DD / 4;
        prep_split<<<(w2 + 255) / 256, 256>>>(eW2, (__nv_bfloat16*)e2h, (__nv_bfloat16*)e2l, w2);
        int w3 = 2 * DD * DD / 4;
        prep_split<<<(w3 + 255) / 256, 256>>>(nW1, (__nv_bfloat16*)n1h, (__nv_bfloat16*)n1l, w3);
        prep_split<<<(w2 + 255) / 256, 256>>>(nW2, (__nv_bfloat16*)n2h, (__nv_bfloat16*)n2l, w2);
    }

    const int eblocks = (E + EB - 1) / EB;
    edge_kernel<<<eblocks, NTHR, SMEM_BYTES>>>(ea, ei, eb1, eb2, eg, ebt, eout, E);

    const int nblocks = (Nn + EB - 1) / EB;
    node_kernel<<<nblocks, NTHR, SMEM_BYTES>>>(x, nb1, nb2, ng, nbt, xout, Nn);

    rms_kernel<<<1, 128>>>(Nn);

    const int n4 = Nn * DD / 4;
    finalize_kernel<<<(n4 + 255) / 256, 256>>>(xout, n4);
}

// round 9
// speedup vs baseline: 1.6925x; 1.6925x over previous
#include <cuda_runtime.h>
#include <cuda_fp16.h>
#include <cstdint>

#define DD   128
#define EB   128
#define NTHR 256
#define MAXN 100000

// ---- dynamic smem layout (bytes) ------------------------------------------
// GEMM1:   A (128 x 72 fp16) @OFF_A, W chunks (64 x 136 fp16) @OFF_W0/OFF_W1
// hidden:  Hh (128 x 136 fp16) @0
// GEMM2:   A = Hh @0, W chunks @OFF_W0/OFF_W1 (both resident)
// epilogue: Hs fp32 (128 x 132) @0  (overlays Hh + W0; both dead by then)
#define OFF_H    0
#define OFF_W0   34816
#define OFF_W1   52224
#define OFF_A    69632
#define OFF_TAIL 88064
// tail: +0 sIdx(256 int)/csum(129 f) | +1024 muS | +1536 invS
//       +2048 b1S | +2560 b2S | +3072 gmaS | +3584 btaS
#define SMEM_BYTES 92160

// ---- device global scratch ------------------------------------------------
__device__ float g_agg[(size_t)MAXN * DD];
__device__ float g_colsum[DD];
__device__ float g_sumsq[1];
__device__ float g_mean[DD];
__device__ float g_invrms[1];
__device__ __half g_xf[(size_t)MAXN * DD];      // x in fp16
__device__ __half g_eW1f[3 * DD * DD];
__device__ __half g_eW2f[DD * DD];
__device__ __half g_nW1f[2 * DD * DD];
__device__ __half g_nW2f[DD * DD];

// ---- helpers --------------------------------------------------------------
static __device__ __forceinline__ void warp_red2(float& a, float& b) {
#pragma unroll
    for (int o = 16; o > 0; o >>= 1) {
        a += __shfl_xor_sync(0xffffffffu, a, o);
        b += __shfl_xor_sync(0xffffffffu, b, o);
    }
}
static __device__ __forceinline__ void ldsm4(unsigned r[4], unsigned addr) {
    asm volatile("ldmatrix.sync.aligned.m8n8.x4.shared.b16 {%0,%1,%2,%3}, [%4];\n"
                 : "=r"(r[0]), "=r"(r[1]), "=r"(r[2]), "=r"(r[3]) : "r"(addr));
}
static __device__ __forceinline__ void ldsm4t(unsigned r[4], unsigned addr) {
    asm volatile("ldmatrix.sync.aligned.m8n8.x4.trans.shared.b16 {%0,%1,%2,%3}, [%4];\n"
                 : "=r"(r[0]), "=r"(r[1]), "=r"(r[2]), "=r"(r[3]) : "r"(addr));
}
static __device__ __forceinline__ void mma16816(float d[4], const unsigned a[4],
                                                unsigned b0, unsigned b1) {
    asm volatile("mma.sync.aligned.m16n8k16.row.col.f32.f16.f16.f32 "
                 "{%0,%1,%2,%3}, {%4,%5,%6,%7}, {%8,%9}, {%0,%1,%2,%3};\n"
                 : "+f"(d[0]), "+f"(d[1]), "+f"(d[2]), "+f"(d[3])
                 : "r"(a[0]), "r"(a[1]), "r"(a[2]), "r"(a[3]), "r"(b0), "r"(b1));
}
static __device__ __forceinline__ void cp16(unsigned saddr, const void* g) {
    asm volatile("cp.async.cg.shared.global [%0], [%1], 16;\n" :: "r"(saddr), "l"(g));
}
static __device__ __forceinline__ void cp_commit() { asm volatile("cp.async.commit_group;\n"); }
static __device__ __forceinline__ void cp_wait0()  { asm volatile("cp.async.wait_group 0;\n" ::: "memory"); }
static __device__ __forceinline__ void red4(float* p, float4 v) {
    asm volatile("red.global.add.v4.f32 [%0], {%1,%2,%3,%4};\n"
                 :: "l"(p), "f"(v.x), "f"(v.y), "f"(v.z), "f"(v.w) : "memory");
}

// store float4 as 4 fp16 at [r][c], element stride STR
template <int STR>
static __device__ __forceinline__ void h4_store(__half* H, int r, int c, float4 v) {
    __half2 a = __floats2half2_rn(v.x, v.y);
    __half2 b = __floats2half2_rn(v.z, v.w);
    *(__half2*)(H + r * STR + c)     = a;
    *(__half2*)(H + r * STR + c + 2) = b;
}

// one K=64 chunk, single-pass fp16: acc += A(128x64) * W(64x128)
static __device__ __forceinline__ void mma_chunk64(float acc[2][8][4],
                                                   unsigned aB, int astr, int acol0,
                                                   unsigned wB,
                                                   int wm, int wn, int lane) {
    const int ar  = lane & 15;
    const int asl = (lane >> 4) * 8;
#pragma unroll
    for (int ks = 0; ks < 4; ks++) {
        unsigned a[2][4];
        const int acol = acol0 + ks * 16 + asl;
#pragma unroll
        for (int mt = 0; mt < 2; mt++) {
            int arow = wm * 32 + mt * 16 + ar;
            ldsm4(a[mt], aB + (unsigned)((arow * astr + acol) * 2));
        }
        const int brow = ks * 16 + ar;
#pragma unroll
        for (int np = 0; np < 4; np++) {
            int bcol = wn * 64 + np * 16 + asl;
            unsigned b[4];
            ldsm4t(b, wB + (unsigned)((brow * 136 + bcol) * 2));
#pragma unroll
            for (int mt = 0; mt < 2; mt++) {
                mma16816(acc[mt][2 * np],     a[mt], b[0], b[1]);
                mma16816(acc[mt][2 * np + 1], a[mt], b[2], b[3]);
            }
        }
    }
}

// cp.async one 64x128 fp16 weight chunk into buffer at wbase (stride 136)
// 64 rows * 128 cols * 2B = 16384 B = 1024 cp16 -> 4 iters of 256 threads
static __device__ __forceinline__ void load_w64(unsigned wbase, const __half* W, int tid) {
#pragma unroll
    for (int i = 0; i < 4; i++) {
        int idx = tid + NTHR * i;
        int r = idx >> 4, u = (idx & 15) * 8;
        cp16(wbase + (unsigned)((r * 136 + u) * 2), W + r * DD + u);
    }
}

// hidden: bias+relu -> fp16 Hh (stride 136); zero acc
static __device__ __forceinline__ void hidden_store(float acc[2][8][4], __half* Hh,
                                                    const float* b1S, int wm, int wn, int lane) {
    const int g = lane >> 2, t = lane & 3;
#pragma unroll
    for (int mt = 0; mt < 2; mt++) {
#pragma unroll
        for (int nt = 0; nt < 8; nt++) {
            int col = wn * 64 + nt * 8 + t * 2;
            float bx = b1S[col], by = b1S[col + 1];
            int r0 = wm * 32 + mt * 16 + g;
            *(__half2*)(Hh + r0 * 136 + col) =
                __floats2half2_rn(fmaxf(acc[mt][nt][0] + bx, 0.f), fmaxf(acc[mt][nt][1] + by, 0.f));
            *(__half2*)(Hh + (r0 + 8) * 136 + col) =
                __floats2half2_rn(fmaxf(acc[mt][nt][2] + bx, 0.f), fmaxf(acc[mt][nt][3] + by, 0.f));
            acc[mt][nt][0] = acc[mt][nt][1] = acc[mt][nt][2] = acc[mt][nt][3] = 0.f;
        }
    }
}

// acc + b2 -> Hs fp32 (stride 132)
static __device__ __forceinline__ void out_store(const float acc[2][8][4], float* Hs,
                                                 const float* b2S, int wm, int wn, int lane) {
    const int g = lane >> 2, t = lane & 3;
#pragma unroll
    for (int mt = 0; mt < 2; mt++) {
#pragma unroll
        for (int nt = 0; nt < 8; nt++) {
            int col = wn * 64 + nt * 8 + t * 2;
            float bx = b2S[col], by = b2S[col + 1];
            int r0 = wm * 32 + mt * 16 + g;
            *(float2*)(Hs + r0 * 132 + col)       = make_float2(acc[mt][nt][0] + bx, acc[mt][nt][1] + by);
            *(float2*)(Hs + (r0 + 8) * 132 + col) = make_float2(acc[mt][nt][2] + bx, acc[mt][nt][3] + by);
        }
    }
}

static __device__ __forceinline__ void stats_rows(const float* Hs, float* muS, float* invS,
                                                  int wid, int lane) {
#pragma unroll 1
    for (int j = 0; j < 16; j++) {
        int r = wid * 16 + j;
        float s = 0.f, sq = 0.f;
#pragma unroll
        for (int q = 0; q < 4; q++) {
            float v = Hs[r * 132 + lane + 32 * q];
            s += v; sq += v * v;
        }
        warp_red2(s, sq);
        if (lane == 0) {
            float mu = s * (1.f / 128.f);
            muS[r]  = mu;
            invS[r] = rsqrtf(sq * (1.f / 128.f) - mu * mu + 1e-5f);
        }
    }
}

// ---- prep: fp32 -> fp16 ---------------------------------------------------
__global__ void prep_half(const float* __restrict__ src, __half* __restrict__ h, int n4) {
    int i = blockIdx.x * blockDim.x + threadIdx.x;
    if (i >= n4) return;
    float4 v = ((const float4*)src)[i];
    ((__half2*)h)[2 * i]     = __floats2half2_rn(v.x, v.y);
    ((__half2*)h)[2 * i + 1] = __floats2half2_rn(v.z, v.w);
}

// ---------------------------------------------------------------------------
__global__ void __launch_bounds__(NTHR, 2)
edge_kernel(const float* __restrict__ ea,
            const int* __restrict__ ei,
            const float* __restrict__ b1, const float* __restrict__ b2,
            const float* __restrict__ gma, const float* __restrict__ bta,
            float* __restrict__ eout, int E)
{
    extern __shared__ char smc[];
    const unsigned sbase = (unsigned)__cvta_generic_to_shared(smc);
    int*   sIdx = (int*)(smc + OFF_TAIL);
    float* muS  = (float*)(smc + OFF_TAIL + 1024);
    float* invS = (float*)(smc + OFF_TAIL + 1536);
    float* b1S  = (float*)(smc + OFF_TAIL + 2048);
    float* b2S  = (float*)(smc + OFF_TAIL + 2560);
    float* gmaS = (float*)(smc + OFF_TAIL + 3072);
    float* btaS = (float*)(smc + OFF_TAIL + 3584);
    float* Hs   = (float*)smc;

    const int tid = threadIdx.x, lane = tid & 31, wid = tid >> 5;
    const int wm = wid & 3, wn = wid >> 2;
    const int eb = blockIdx.x * EB;
    const int Eloc = min(EB, E - eb);

    if (tid < 128) {
        sIdx[tid] = (tid < Eloc) ? ei[eb + tid] : 0;
        b1S[tid] = b1[tid]; b2S[tid] = b2[tid];
        gmaS[tid] = gma[tid]; btaS[tid] = bta[tid];
    } else {
        int t2 = tid - 128;
        sIdx[tid] = (t2 < Eloc) ? ei[E + eb + t2] : 0;
    }
    __syncthreads();

    // A chunk loader: 0-3 = gathered x (fp16 cp.async), 4-5 = ea (convert)
    // x-gather: 128 rows * 64 cols fp16 = 1024 cp16 -> 4 iters
    auto loadA = [&](int chunk) {
        if (chunk < 4) {
            const int seg = chunk >> 1, c0 = (chunk & 1) * 64;
#pragma unroll
            for (int i = 0; i < 4; i++) {
                int idx = tid + NTHR * i;
                int r = idx >> 3, u = (idx & 7) * 8;
                size_t grow = (size_t)sIdx[seg * 128 + r] * DD + c0 + u;
                cp16(sbase + OFF_A + (unsigned)((r * 72 + u) * 2), g_xf + grow);
            }
        } else {
            const int c0 = (chunk - 4) * 64;
            __half* Ah = (__half*)(smc + OFF_A);
#pragma unroll
            for (int i = 0; i < 8; i++) {
                int idx = tid + NTHR * i;
                int r = idx >> 4, c4 = (idx & 15) * 4;
                if (r < Eloc) {
                    float4 v = *(const float4*)(ea + (size_t)(eb + r) * DD + c0 + c4);
                    h4_store<72>(Ah, r, c4, v);
                }
            }
        }
    };

    float acc[2][8][4];
#pragma unroll
    for (int mt = 0; mt < 2; mt++)
#pragma unroll
        for (int nt = 0; nt < 8; nt++)
#pragma unroll
            for (int q = 0; q < 4; q++) acc[mt][nt][q] = 0.f;

    // prologue
    load_w64(sbase + OFF_W0, g_eW1f, tid);
    loadA(0);
    cp_commit(); cp_wait0();
    __syncthreads();

    // ---- GEMM1: 6 chunks, W double-buffered ----
#pragma unroll 1
    for (int c = 0; c < 6; c++) {
        if (c < 5) {
            unsigned wb = ((c + 1) & 1) ? OFF_W1 : OFF_W0;
            load_w64(sbase + wb, g_eW1f + (c + 1) * 64 * DD, tid);
            cp_commit();
        }
        unsigned wb = (c & 1) ? OFF_W1 : OFF_W0;
        mma_chunk64(acc, sbase + OFF_A, 72, 0, sbase + wb, wm, wn, lane);
        __syncthreads();
        if (c < 5) {
            loadA(c + 1);
            cp_commit(); cp_wait0();
            __syncthreads();
        }
    }

    // ---- hidden + GEMM2 (both W chunks resident) ----
    load_w64(sbase + OFF_W0, g_eW2f, tid);
    load_w64(sbase + OFF_W1, g_eW2f + 64 * DD, tid);
    cp_commit();
    hidden_store(acc, (__half*)(smc + OFF_H), b1S, wm, wn, lane);
    cp_wait0();
    __syncthreads();
    mma_chunk64(acc, sbase + OFF_H, 136, 0,  sbase + OFF_W0, wm, wn, lane);
    mma_chunk64(acc, sbase + OFF_H, 136, 64, sbase + OFF_W1, wm, wn, lane);
    __syncthreads();

    // ---- epilogue ----
    out_store(acc, Hs, b2S, wm, wn, lane);
    __syncthreads();
    stats_rows(Hs, muS, invS, wid, lane);
    __syncthreads();

    const int c4 = 4 * lane;
    float4 g4 = *(const float4*)(gmaS + c4);
    float4 t4 = *(const float4*)(btaS + c4);
#pragma unroll 1
    for (int j = 0; j < 16; j++) {
        int r = wid * 16 + j;
        if (r >= Eloc) continue;
        size_t ge = (size_t)(eb + r);
        float mu = muS[r], inv = invS[r];
        float4 v = *(const float4*)(Hs + r * 132 + c4);
        float4 o;
        o.x = (v.x - mu) * inv * g4.x + t4.x;
        o.y = (v.y - mu) * inv * g4.y + t4.y;
        o.z = (v.z - mu) * inv * g4.z + t4.z;
        o.w = (v.w - mu) * inv * g4.w + t4.w;
        float4 e4 = *(const float4*)(ea + ge * DD + c4);
        e4.x += o.x; e4.y += o.y; e4.z += o.z; e4.w += o.w;
        *(float4*)(eout + ge * DD + c4) = e4;
        red4(&g_agg[(size_t)sIdx[128 + r] * DD + c4], o);
    }
}

// ---------------------------------------------------------------------------
__global__ void __launch_bounds__(NTHR, 2)
node_kernel(const float* __restrict__ x,
            const float* __restrict__ b1, const float* __restrict__ b2,
            const float* __restrict__ gma, const float* __restrict__ bta,
            float* __restrict__ xpre, int Nn)
{
    extern __shared__ char smc[];
    const unsigned sbase = (unsigned)__cvta_generic_to_shared(smc);
    float* csum_s = (float*)(smc + OFF_TAIL);
    float* muS  = (float*)(smc + OFF_TAIL + 1024);
    float* invS = (float*)(smc + OFF_TAIL + 1536);
    float* b1S  = (float*)(smc + OFF_TAIL + 2048);
    float* b2S  = (float*)(smc + OFF_TAIL + 2560);
    float* gmaS = (float*)(smc + OFF_TAIL + 3072);
    float* btaS = (float*)(smc + OFF_TAIL + 3584);
    float* Hs   = (float*)smc;

    const int tid = threadIdx.x, lane = tid & 31, wid = tid >> 5;
    const int wm = wid & 3, wn = wid >> 2;
    const int nb = blockIdx.x * EB;
    const int Nloc = min(EB, Nn - nb);

    if (tid < 128) {
        b1S[tid] = b1[tid]; b2S[tid] = b2[tid];
        gmaS[tid] = gma[tid]; btaS[tid] = bta[tid];
    }
    if (tid < 129) csum_s[tid] = 0.f;
    __syncthreads();

    auto loadA = [&](int chunk) {
        const int c0 = (chunk & 1) * 64;
        if (chunk < 2) {
#pragma unroll
            for (int i = 0; i < 4; i++) {
                int idx = tid + NTHR * i;
                int r = idx >> 3, u = (idx & 7) * 8;
                if (r < Nloc) {
                    size_t grow = (size_t)(nb + r) * DD + c0 + u;
                    cp16(sbase + OFF_A + (unsigned)((r * 72 + u) * 2), g_xf + grow);
                }
            }
        } else {
            __half* Ah = (__half*)(smc + OFF_A);
#pragma unroll
            for (int i = 0; i < 8; i++) {
                int idx = tid + NTHR * i;
                int r = idx >> 4, c4 = (idx & 15) * 4;
                if (r < Nloc) {
                    float4 v = *(const float4*)(g_agg + (size_t)(nb + r) * DD + c0 + c4);
                    h4_store<72>(Ah, r, c4, v);
                }
            }
        }
    };

    float acc[2][8][4];
#pragma unroll
    for (int mt = 0; mt < 2; mt++)
#pragma unroll
        for (int nt = 0; nt < 8; nt++)
#pragma unroll
            for (int q = 0; q < 4; q++) acc[mt][nt][q] = 0.f;

    load_w64(sbase + OFF_W0, g_nW1f, tid);
    loadA(0);
    cp_commit(); cp_wait0();
    __syncthreads();

    // ---- GEMM1: 4 chunks ----
#pragma unroll 1
    for (int c = 0; c < 4; c++) {
        if (c < 3) {
            unsigned wb = ((c + 1) & 1) ? OFF_W1 : OFF_W0;
            load_w64(sbase + wb, g_nW1f + (c + 1) * 64 * DD, tid);
            cp_commit();
        }
        unsigned wb = (c & 1) ? OFF_W1 : OFF_W0;
        mma_chunk64(acc, sbase + OFF_A, 72, 0, sbase + wb, wm, wn, lane);
        __syncthreads();
        if (c < 3) {
            loadA(c + 1);
            cp_commit(); cp_wait0();
            __syncthreads();
        }
    }

    load_w64(sbase + OFF_W0, g_nW2f, tid);
    load_w64(sbase + OFF_W1, g_nW2f + 64 * DD, tid);
    cp_commit();
    hidden_store(acc, (__half*)(smc + OFF_H), b1S, wm, wn, lane);
    cp_wait0();
    __syncthreads();
    mma_chunk64(acc, sbase + OFF_H, 136, 0,  sbase + OFF_W0, wm, wn, lane);
    mma_chunk64(acc, sbase + OFF_H, 136, 64, sbase + OFF_W1, wm, wn, lane);
    __syncthreads();

    out_store(acc, Hs, b2S, wm, wn, lane);
    __syncthreads();
    stats_rows(Hs, muS, invS, wid, lane);
    __syncthreads();

    // ---- LN + residual + PairNorm partials ----
    const int c4 = 4 * lane;
    float4 g4 = *(const float4*)(gmaS + c4);
    float4 t4 = *(const float4*)(btaS + c4);
    float4 cs = make_float4(0.f, 0.f, 0.f, 0.f);
    float sq_acc = 0.f;
#pragma unroll 1
    for (int j = 0; j < 16; j++) {
        int r = wid * 16 + j;
        if (r >= Nloc) continue;
        size_t gn = (size_t)(nb + r);
        float mu = muS[r], inv = invS[r];
        float4 v = *(const float4*)(Hs + r * 132 + c4);
        float4 xv = *(const float4*)(x + gn * DD + c4);
        float4 xp;
        xp.x = xv.x + (v.x - mu) * inv * g4.x + t4.x;
        xp.y = xv.y + (v.y - mu) * inv * g4.y + t4.y;
        xp.z = xv.z + (v.z - mu) * inv * g4.z + t4.z;
        xp.w = xv.w + (v.w - mu) * inv * g4.w + t4.w;
        *(float4*)(xpre + gn * DD + c4) = xp;
        cs.x += xp.x; cs.y += xp.y; cs.z += xp.z; cs.w += xp.w;
        sq_acc += xp.x * xp.x + xp.y * xp.y + xp.z * xp.z + xp.w * xp.w;
    }
    atomicAdd(&csum_s[c4 + 0], cs.x);
    atomicAdd(&csum_s[c4 + 1], cs.y);
    atomicAdd(&csum_s[c4 + 2], cs.z);
    atomicAdd(&csum_s[c4 + 3], cs.w);
#pragma unroll
    for (int o = 16; o > 0; o >>= 1) sq_acc += __shfl_xor_sync(0xffffffffu, sq_acc, o);
    if (lane == 0) atomicAdd(&csum_s[128], sq_acc);
    __syncthreads();
    if (tid < 128)       atomicAdd(&g_colsum[tid], csum_s[tid]);
    else if (tid == 128) atomicAdd(&g_sumsq[0],    csum_s[128]);
}

// ---------------------------------------------------------------------------
__global__ void rms_kernel(int Nn)
{
    __shared__ float red[128];
    int c = threadIdx.x;
    float m = g_colsum[c] / (float)Nn;
    g_mean[c] = m;
    red[c] = m * m;
    __syncthreads();
    for (int o = 64; o > 0; o >>= 1) {
        if (c < o) red[c] += red[c + o];
        __syncthreads();
    }
    if (c == 0) {
        float ssc = g_sumsq[0] - (float)Nn * red[0];
        float rms = sqrtf(ssc / (float)Nn) + 1e-8f;
        g_invrms[0] = 1.0f / rms;
    }
}

__global__ void finalize_kernel(float* __restrict__ xout, int n4)
{
    int i = blockIdx.x * blockDim.x + threadIdx.x;
    if (i < n4) {
        float4 v = ((const float4*)xout)[i];
        int c = (i * 4) & 127;
        float inv = g_invrms[0];
        v.x = (v.x - g_mean[c])     * inv;
        v.y = (v.y - g_mean[c + 1]) * inv;
        v.z = (v.z - g_mean[c + 2]) * inv;
        v.w = (v.w - g_mean[c + 3]) * inv;
        ((float4*)xout)[i] = v;
    }
}

// ---------------------------------------------------------------------------
extern "C" void kernel_launch(void* const* d_in, const int* in_sizes, int n_in,
                              void* d_out, int out_size)
{
    const float* x   = (const float*)d_in[0];
    const float* ea  = (const float*)d_in[1];
    const int*   ei  = (const int*)d_in[2];      // int32 (JAX x64 disabled)
    const float* eW1 = (const float*)d_in[3];
    const float* eb1 = (const float*)d_in[4];
    const float* eW2 = (const float*)d_in[5];
    const float* eb2 = (const float*)d_in[6];
    const float* eg  = (const float*)d_in[7];
    const float* ebt = (const float*)d_in[8];
    const float* nW1 = (const float*)d_in[9];
    const float* nb1 = (const float*)d_in[10];
    const float* nW2 = (const float*)d_in[11];
    const float* nb2 = (const float*)d_in[12];
    const float* ng  = (const float*)d_in[13];
    const float* nbt = (const float*)d_in[14];

    const int Nn = in_sizes[0] / DD;
    const int E  = in_sizes[1] / DD;

    float* xout = (float*)d_out;
    float* eout = xout + (size_t)Nn * DD;

    cudaFuncSetAttribute(edge_kernel, cudaFuncAttributeMaxDynamicSharedMemorySize, SMEM_BYTES);
    cudaFuncSetAttribute(node_kernel, cudaFuncAttributeMaxDynamicSharedMemorySize, SMEM_BYTES);

    void *aggp, *csp, *sqp, *xfp, *e1, *e2, *n1, *n2;
    cudaGetSymbolAddress(&aggp, g_agg);
    cudaGetSymbolAddress(&csp,  g_colsum);
    cudaGetSymbolAddress(&sqp,  g_sumsq);
    cudaGetSymbolAddress(&xfp,  g_xf);
    cudaGetSymbolAddress(&e1, g_eW1f);
    cudaGetSymbolAddress(&e2, g_eW2f);
    cudaGetSymbolAddress(&n1, g_nW1f);
    cudaGetSymbolAddress(&n2, g_nW2f);

    cudaMemsetAsync(aggp, 0, (size_t)Nn * DD * sizeof(float));
    cudaMemsetAsync(csp,  0, DD * sizeof(float));
    cudaMemsetAsync(sqp,  0, sizeof(float));

    {
        int n4 = Nn * DD / 4;
        prep_half<<<(n4 + 255) / 256, 256>>>(x, (__half*)xfp, n4);
        int w1 = 3 * DD * DD / 4;
        prep_half<<<(w1 + 255) / 256, 256>>>(eW1, (__half*)e1, w1);
        int w2 = DD * DD / 4;
        prep_half<<<(w2 + 255) / 256, 256>>>(eW2, (__half*)e2, w2);
        int w3 = 2 * DD * DD / 4;
        prep_half<<<(w3 + 255) / 256, 256>>>(nW1, (__half*)n1, w3);
        prep_half<<<(w2 + 255) / 256, 256>>>(nW2, (__half*)n2, w2);
    }

    const int eblocks = (E + EB - 1) / EB;
    edge_kernel<<<eblocks, NTHR, SMEM_BYTES>>>(ea, ei, eb1, eb2, eg, ebt, eout, E);

    const int nblocks = (Nn + EB - 1) / EB;
    node_kernel<<<nblocks, NTHR, SMEM_BYTES>>>(x, nb1, nb2, ng, nbt, xout, Nn);

    rms_kernel<<<1, 128>>>(Nn);

    const int n4 = Nn * DD / 4;
    finalize_kernel<<<(n4 + 255) / 256, 256>>>(xout, n4);
}

// round 10
// speedup vs baseline: 1.7341x; 1.0246x over previous
#include <cuda_runtime.h>
#include <cuda_fp16.h>
#include <cstdint>

#define DD   128
#define EB   128
#define NTHR 256
#define MAXN 100000

// ---- dynamic smem layout (bytes) ------------------------------------------
// GEMM1:   A bufs (128 x 72 fp16 = 18432) @OFF_A0/OFF_A1,
//          W bufs (64 x 136 fp16 = 17408) @OFF_W0/OFF_W1
// GEMM2:   Hh (128 x 136 fp16 = 34816) @OFF_H; W chunks prefetched @OFF_A0/OFF_W0
// epilogue: Hs fp32 (128 x 132 = 67584) @0 (overlays Hh+W0+W1; all dead)
#define OFF_H    0
#define OFF_W0   34816
#define OFF_W1   52224
#define OFF_A0   69632
#define OFF_A1   88064
#define OFF_TAIL 106496
// tail: +0 sIdx(256 int)/csum(129 f) | +1024 muS | +1536 invS
//       +2048 b1S | +2560 b2S | +3072 gmaS | +3584 btaS
#define SMEM_BYTES 110592

// ---- device global scratch ------------------------------------------------
__device__ float g_agg[(size_t)MAXN * DD];
__device__ float g_colsum[DD];
__device__ float g_sumsq[1];
__device__ float g_mean[DD];
__device__ float g_invrms[1];
__device__ __half g_xf[(size_t)MAXN * DD];      // x in fp16
__device__ __half g_eW1f[3 * DD * DD];
__device__ __half g_eW2f[DD * DD];
__device__ __half g_nW1f[2 * DD * DD];
__device__ __half g_nW2f[DD * DD];

// ---- helpers --------------------------------------------------------------
static __device__ __forceinline__ void warp_red2(float& a, float& b) {
#pragma unroll
    for (int o = 16; o > 0; o >>= 1) {
        a += __shfl_xor_sync(0xffffffffu, a, o);
        b += __shfl_xor_sync(0xffffffffu, b, o);
    }
}
static __device__ __forceinline__ void ldsm4(unsigned r[4], unsigned addr) {
    asm volatile("ldmatrix.sync.aligned.m8n8.x4.shared.b16 {%0,%1,%2,%3}, [%4];\n"
                 : "=r"(r[0]), "=r"(r[1]), "=r"(r[2]), "=r"(r[3]) : "r"(addr));
}
static __device__ __forceinline__ void ldsm4t(unsigned r[4], unsigned addr) {
    asm volatile("ldmatrix.sync.aligned.m8n8.x4.trans.shared.b16 {%0,%1,%2,%3}, [%4];\n"
                 : "=r"(r[0]), "=r"(r[1]), "=r"(r[2]), "=r"(r[3]) : "r"(addr));
}
static __device__ __forceinline__ void mma16816(float d[4], const unsigned a[4],
                                                unsigned b0, unsigned b1) {
    asm volatile("mma.sync.aligned.m16n8k16.row.col.f32.f16.f16.f32 "
                 "{%0,%1,%2,%3}, {%4,%5,%6,%7}, {%8,%9}, {%0,%1,%2,%3};\n"
                 : "+f"(d[0]), "+f"(d[1]), "+f"(d[2]), "+f"(d[3])
                 : "r"(a[0]), "r"(a[1]), "r"(a[2]), "r"(a[3]), "r"(b0), "r"(b1));
}
static __device__ __forceinline__ void cp16(unsigned saddr, const void* g) {
    asm volatile("cp.async.cg.shared.global [%0], [%1], 16;\n" :: "r"(saddr), "l"(g));
}
static __device__ __forceinline__ void cp_commit() { asm volatile("cp.async.commit_group;\n"); }
static __device__ __forceinline__ void cp_wait0()  { asm volatile("cp.async.wait_group 0;\n" ::: "memory"); }
static __device__ __forceinline__ void red4(float* p, float4 v) {
    asm volatile("red.global.add.v4.f32 [%0], {%1,%2,%3,%4};\n"
                 :: "l"(p), "f"(v.x), "f"(v.y), "f"(v.z), "f"(v.w) : "memory");
}

// store float4 as 4 fp16 at [r][c], element stride STR
template <int STR>
static __device__ __forceinline__ void h4_store(__half* H, int r, int c, float4 v) {
    __half2 a = __floats2half2_rn(v.x, v.y);
    __half2 b = __floats2half2_rn(v.z, v.w);
    *(__half2*)(H + r * STR + c)     = a;
    *(__half2*)(H + r * STR + c + 2) = b;
}

// one K=64 chunk, single-pass fp16: acc += A(128x64) * W(64x128)
static __device__ __forceinline__ void mma_chunk64(float acc[2][8][4],
                                                   unsigned aB, int astr, int acol0,
                                                   unsigned wB,
                                                   int wm, int wn, int lane) {
    const int ar  = lane & 15;
    const int asl = (lane >> 4) * 8;
#pragma unroll
    for (int ks = 0; ks < 4; ks++) {
        unsigned a[2][4];
        const int acol = acol0 + ks * 16 + asl;
#pragma unroll
        for (int mt = 0; mt < 2; mt++) {
            int arow = wm * 32 + mt * 16 + ar;
            ldsm4(a[mt], aB + (unsigned)((arow * astr + acol) * 2));
        }
        const int brow = ks * 16 + ar;
#pragma unroll
        for (int np = 0; np < 4; np++) {
            int bcol = wn * 64 + np * 16 + asl;
            unsigned b[4];
            ldsm4t(b, wB + (unsigned)((brow * 136 + bcol) * 2));
#pragma unroll
            for (int mt = 0; mt < 2; mt++) {
                mma16816(acc[mt][2 * np],     a[mt], b[0], b[1]);
                mma16816(acc[mt][2 * np + 1], a[mt], b[2], b[3]);
            }
        }
    }
}

// cp.async one 64x128 fp16 weight chunk into buffer at wbase (stride 136)
static __device__ __forceinline__ void load_w64(unsigned wbase, const __half* W, int tid) {
#pragma unroll
    for (int i = 0; i < 4; i++) {
        int idx = tid + NTHR * i;
        int r = idx >> 4, u = (idx & 15) * 8;
        cp16(wbase + (unsigned)((r * 136 + u) * 2), W + r * DD + u);
    }
}

// hidden: bias+relu -> fp16 Hh (stride 136); zero acc
static __device__ __forceinline__ void hidden_store(float acc[2][8][4], __half* Hh,
                                                    const float* b1S, int wm, int wn, int lane) {
    const int g = lane >> 2, t = lane & 3;
#pragma unroll
    for (int mt = 0; mt < 2; mt++) {
#pragma unroll
        for (int nt = 0; nt < 8; nt++) {
            int col = wn * 64 + nt * 8 + t * 2;
            float bx = b1S[col], by = b1S[col + 1];
            int r0 = wm * 32 + mt * 16 + g;
            *(__half2*)(Hh + r0 * 136 + col) =
                __floats2half2_rn(fmaxf(acc[mt][nt][0] + bx, 0.f), fmaxf(acc[mt][nt][1] + by, 0.f));
            *(__half2*)(Hh + (r0 + 8) * 136 + col) =
                __floats2half2_rn(fmaxf(acc[mt][nt][2] + bx, 0.f), fmaxf(acc[mt][nt][3] + by, 0.f));
            acc[mt][nt][0] = acc[mt][nt][1] = acc[mt][nt][2] = acc[mt][nt][3] = 0.f;
        }
    }
}

// acc + b2 -> Hs fp32 (stride 132)
static __device__ __forceinline__ void out_store(const float acc[2][8][4], float* Hs,
                                                 const float* b2S, int wm, int wn, int lane) {
    const int g = lane >> 2, t = lane & 3;
#pragma unroll
    for (int mt = 0; mt < 2; mt++) {
#pragma unroll
        for (int nt = 0; nt < 8; nt++) {
            int col = wn * 64 + nt * 8 + t * 2;
            float bx = b2S[col], by = b2S[col + 1];
            int r0 = wm * 32 + mt * 16 + g;
            *(float2*)(Hs + r0 * 132 + col)       = make_float2(acc[mt][nt][0] + bx, acc[mt][nt][1] + by);
            *(float2*)(Hs + (r0 + 8) * 132 + col) = make_float2(acc[mt][nt][2] + bx, acc[mt][nt][3] + by);
        }
    }
}

static __device__ __forceinline__ void stats_rows(const float* Hs, float* muS, float* invS,
                                                  int wid, int lane) {
#pragma unroll 1
    for (int j = 0; j < 16; j++) {
        int r = wid * 16 + j;
        float s = 0.f, sq = 0.f;
#pragma unroll
        for (int q = 0; q < 4; q++) {
            float v = Hs[r * 132 + lane + 32 * q];
            s += v; sq += v * v;
        }
        warp_red2(s, sq);
        if (lane == 0) {
            float mu = s * (1.f / 128.f);
            muS[r]  = mu;
            invS[r] = rsqrtf(sq * (1.f / 128.f) - mu * mu + 1e-5f);
        }
    }
}

// ---- prep: fp32 -> fp16 ---------------------------------------------------
__global__ void prep_half(const float* __restrict__ src, __half* __restrict__ h, int n4) {
    int i = blockIdx.x * blockDim.x + threadIdx.x;
    if (i >= n4) return;
    float4 v = ((const float4*)src)[i];
    ((__half2*)h)[2 * i]     = __floats2half2_rn(v.x, v.y);
    ((__half2*)h)[2 * i + 1] = __floats2half2_rn(v.z, v.w);
}

// one launch converts all 4 weight tensors (7*DD*DD fp32 total)
__global__ void prep_weights(const float* __restrict__ eW1, const float* __restrict__ eW2,
                             const float* __restrict__ nW1, const float* __restrict__ nW2) {
    const int W1E = 3 * DD * DD / 4, W2E = DD * DD / 4, W3E = 2 * DD * DD / 4;
    int i = blockIdx.x * blockDim.x + threadIdx.x;
    const float* src; __half* dst; int off;
    if (i < W1E)                       { src = eW1; dst = g_eW1f; off = i; }
    else if (i < W1E + W2E)            { src = eW2; dst = g_eW2f; off = i - W1E; }
    else if (i < W1E + W2E + W3E)      { src = nW1; dst = g_nW1f; off = i - W1E - W2E; }
    else if (i < W1E + 2 * W2E + W3E)  { src = nW2; dst = g_nW2f; off = i - W1E - W2E - W3E; }
    else return;
    float4 v = ((const float4*)src)[off];
    ((__half2*)dst)[2 * off]     = __floats2half2_rn(v.x, v.y);
    ((__half2*)dst)[2 * off + 1] = __floats2half2_rn(v.z, v.w);
}

// ---------------------------------------------------------------------------
__global__ void __launch_bounds__(NTHR, 2)
edge_kernel(const float* __restrict__ ea,
            const int* __restrict__ ei,
            const float* __restrict__ b1, const float* __restrict__ b2,
            const float* __restrict__ gma, const float* __restrict__ bta,
            float* __restrict__ eout, int E)
{
    extern __shared__ char smc[];
    const unsigned sbase = (unsigned)__cvta_generic_to_shared(smc);
    int*   sIdx = (int*)(smc + OFF_TAIL);
    float* muS  = (float*)(smc + OFF_TAIL + 1024);
    float* invS = (float*)(smc + OFF_TAIL + 1536);
    float* b1S  = (float*)(smc + OFF_TAIL + 2048);
    float* b2S  = (float*)(smc + OFF_TAIL + 2560);
    float* gmaS = (float*)(smc + OFF_TAIL + 3072);
    float* btaS = (float*)(smc + OFF_TAIL + 3584);
    float* Hs   = (float*)smc;

    const int tid = threadIdx.x, lane = tid & 31, wid = tid >> 5;
    const int wm = wid & 3, wn = wid >> 2;
    const int eb = blockIdx.x * EB;
    const int Eloc = min(EB, E - eb);

    if (tid < 128) {
        sIdx[tid] = (tid < Eloc) ? ei[eb + tid] : 0;
        b1S[tid] = b1[tid]; b2S[tid] = b2[tid];
        gmaS[tid] = gma[tid]; btaS[tid] = bta[tid];
    } else {
        int t2 = tid - 128;
        sIdx[tid] = (t2 < Eloc) ? ei[E + eb + t2] : 0;
    }
    __syncthreads();

    // A chunk loader into buffer at byte offset abase:
    // chunks 0-3 = gathered x (fp16 cp.async), 4-5 = ea (fp32 -> fp16 convert)
    auto loadA = [&](int chunk, unsigned abase) {
        if (chunk < 4) {
            const int seg = chunk >> 1, c0 = (chunk & 1) * 64;
#pragma unroll
            for (int i = 0; i < 4; i++) {
                int idx = tid + NTHR * i;
                int r = idx >> 3, u = (idx & 7) * 8;
                size_t grow = (size_t)sIdx[seg * 128 + r] * DD + c0 + u;
                cp16(sbase + abase + (unsigned)((r * 72 + u) * 2), g_xf + grow);
            }
        } else {
            const int c0 = (chunk - 4) * 64;
            __half* Ah = (__half*)(smc + abase);
#pragma unroll
            for (int i = 0; i < 8; i++) {
                int idx = tid + NTHR * i;
                int r = idx >> 4, c4 = (idx & 15) * 4;
                if (r < Eloc) {
                    float4 v = *(const float4*)(ea + (size_t)(eb + r) * DD + c0 + c4);
                    h4_store<72>(Ah, r, c4, v);
                }
            }
        }
    };

    float acc[2][8][4];
#pragma unroll
    for (int mt = 0; mt < 2; mt++)
#pragma unroll
        for (int nt = 0; nt < 8; nt++)
#pragma unroll
            for (int q = 0; q < 4; q++) acc[mt][nt][q] = 0.f;

    // prologue: W0 + A0
    load_w64(sbase + OFF_W0, g_eW1f, tid);
    loadA(0, OFF_A0);
    cp_commit(); cp_wait0();
    __syncthreads();

    // ---- GEMM1: 6 chunks, A+W double-buffered; c=5 prefetches GEMM2 W ----
#pragma unroll 1
    for (int c = 0; c < 6; c++) {
        if (c < 5) {
            unsigned wb = ((c + 1) & 1) ? OFF_W1 : OFF_W0;
            unsigned ab = ((c + 1) & 1) ? OFF_A1 : OFF_A0;
            load_w64(sbase + wb, g_eW1f + (c + 1) * 64 * DD, tid);
            loadA(c + 1, ab);
        } else {
            // c=5 uses W1/A1; W0 and A0 are dead -> prefetch GEMM2 weights
            load_w64(sbase + OFF_A0, g_eW2f, tid);
            load_w64(sbase + OFF_W0, g_eW2f + 64 * DD, tid);
        }
        cp_commit();
        unsigned wb = (c & 1) ? OFF_W1 : OFF_W0;
        unsigned ab = (c & 1) ? OFF_A1 : OFF_A0;
        mma_chunk64(acc, sbase + ab, 72, 0, sbase + wb, wm, wn, lane);
        if (c < 5) { cp_wait0(); __syncthreads(); }
    }

    // ---- hidden (writes Hh @0, disjoint from all live buffers) ----
    hidden_store(acc, (__half*)(smc + OFF_H), b1S, wm, wn, lane);
    cp_wait0();
    __syncthreads();

    // ---- GEMM2: W chunks already resident at A0/W0 ----
    mma_chunk64(acc, sbase + OFF_H, 136, 0,  sbase + OFF_A0, wm, wn, lane);
    mma_chunk64(acc, sbase + OFF_H, 136, 64, sbase + OFF_W0, wm, wn, lane);
    __syncthreads();

    // ---- epilogue ----
    out_store(acc, Hs, b2S, wm, wn, lane);
    __syncthreads();
    stats_rows(Hs, muS, invS, wid, lane);
    __syncthreads();

    const int c4 = 4 * lane;
    float4 g4 = *(const float4*)(gmaS + c4);
    float4 t4 = *(const float4*)(btaS + c4);
#pragma unroll 1
    for (int j = 0; j < 16; j++) {
        int r = wid * 16 + j;
        if (r >= Eloc) continue;
        size_t ge = (size_t)(eb + r);
        float mu = muS[r], inv = invS[r];
        float4 v = *(const float4*)(Hs + r * 132 + c4);
        float4 o;
        o.x = (v.x - mu) * inv * g4.x + t4.x;
        o.y = (v.y - mu) * inv * g4.y + t4.y;
        o.z = (v.z - mu) * inv * g4.z + t4.z;
        o.w = (v.w - mu) * inv * g4.w + t4.w;
        float4 e4 = *(const float4*)(ea + ge * DD + c4);
        e4.x += o.x; e4.y += o.y; e4.z += o.z; e4.w += o.w;
        *(float4*)(eout + ge * DD + c4) = e4;
        red4(&g_agg[(size_t)sIdx[128 + r] * DD + c4], o);
    }
}

// ---------------------------------------------------------------------------
__global__ void __launch_bounds__(NTHR, 2)
node_kernel(const float* __restrict__ x,
            const float* __restrict__ b1, const float* __restrict__ b2,
            const float* __restrict__ gma, const float* __restrict__ bta,
            float* __restrict__ xpre, int Nn)
{
    extern __shared__ char smc[];
    const unsigned sbase = (unsigned)__cvta_generic_to_shared(smc);
    float* csum_s = (float*)(smc + OFF_TAIL);
    float* muS  = (float*)(smc + OFF_TAIL + 1024);
    float* invS = (float*)(smc + OFF_TAIL + 1536);
    float* b1S  = (float*)(smc + OFF_TAIL + 2048);
    float* b2S  = (float*)(smc + OFF_TAIL + 2560);
    float* gmaS = (float*)(smc + OFF_TAIL + 3072);
    float* btaS = (float*)(smc + OFF_TAIL + 3584);
    float* Hs   = (float*)smc;

    const int tid = threadIdx.x, lane = tid & 31, wid = tid >> 5;
    const int wm = wid & 3, wn = wid >> 2;
    const int nb = blockIdx.x * EB;
    const int Nloc = min(EB, Nn - nb);

    if (tid < 128) {
        b1S[tid] = b1[tid]; b2S[tid] = b2[tid];
        gmaS[tid] = gma[tid]; btaS[tid] = bta[tid];
    }
    if (tid < 129) csum_s[tid] = 0.f;
    __syncthreads();

    auto loadA = [&](int chunk, unsigned abase) {
        const int c0 = (chunk & 1) * 64;
        if (chunk < 2) {
#pragma unroll
            for (int i = 0; i < 4; i++) {
                int idx = tid + NTHR * i;
                int r = idx >> 3, u = (idx & 7) * 8;
                if (r < Nloc) {
                    size_t grow = (size_t)(nb + r) * DD + c0 + u;
                    cp16(sbase + abase + (unsigned)((r * 72 + u) * 2), g_xf + grow);
                }
            }
        } else {
            __half* Ah = (__half*)(smc + abase);
#pragma unroll
            for (int i = 0; i < 8; i++) {
                int idx = tid + NTHR * i;
                int r = idx >> 4, c4 = (idx & 15) * 4;
                if (r < Nloc) {
                    float4 v = *(const float4*)(g_agg + (size_t)(nb + r) * DD + c0 + c4);
                    h4_store<72>(Ah, r, c4, v);
                }
            }
        }
    };

    float acc[2][8][4];
#pragma unroll
    for (int mt = 0; mt < 2; mt++)
#pragma unroll
        for (int nt = 0; nt < 8; nt++)
#pragma unroll
            for (int q = 0; q < 4; q++) acc[mt][nt][q] = 0.f;

    load_w64(sbase + OFF_W0, g_nW1f, tid);
    loadA(0, OFF_A0);
    cp_commit(); cp_wait0();
    __syncthreads();

    // ---- GEMM1: 4 chunks; c=3 prefetches GEMM2 W ----
#pragma unroll 1
    for (int c = 0; c < 4; c++) {
        if (c < 3) {
            unsigned wb = ((c + 1) & 1) ? OFF_W1 : OFF_W0;
            unsigned ab = ((c + 1) & 1) ? OFF_A1 : OFF_A0;
            load_w64(sbase + wb, g_nW1f + (c + 1) * 64 * DD, tid);
            loadA(c + 1, ab);
        } else {
            load_w64(sbase + OFF_A0, g_nW2f, tid);
            load_w64(sbase + OFF_W0, g_nW2f + 64 * DD, tid);
        }
        cp_commit();
        unsigned wb = (c & 1) ? OFF_W1 : OFF_W0;
        unsigned ab = (c & 1) ? OFF_A1 : OFF_A0;
        mma_chunk64(acc, sbase + ab, 72, 0, sbase + wb, wm, wn, lane);
        if (c < 3) { cp_wait0(); __syncthreads(); }
    }

    hidden_store(acc, (__half*)(smc + OFF_H), b1S, wm, wn, lane);
    cp_wait0();
    __syncthreads();

    mma_chunk64(acc, sbase + OFF_H, 136, 0,  sbase + OFF_A0, wm, wn, lane);
    mma_chunk64(acc, sbase + OFF_H, 136, 64, sbase + OFF_W0, wm, wn, lane);
    __syncthreads();

    out_store(acc, Hs, b2S, wm, wn, lane);
    __syncthreads();
    stats_rows(Hs, muS, invS, wid, lane);
    __syncthreads();

    // ---- LN + residual + PairNorm partials ----
    const int c4 = 4 * lane;
    float4 g4 = *(const float4*)(gmaS + c4);
    float4 t4 = *(const float4*)(btaS + c4);
    float4 cs = make_float4(0.f, 0.f, 0.f, 0.f);
    float sq_acc = 0.f;
#pragma unroll 1
    for (int j = 0; j < 16; j++) {
        int r = wid * 16 + j;
        if (r >= Nloc) continue;
        size_t gn = (size_t)(nb + r);
        float mu = muS[r], inv = invS[r];
        float4 v = *(const float4*)(Hs + r * 132 + c4);
        float4 xv = *(const float4*)(x + gn * DD + c4);
        float4 xp;
        xp.x = xv.x + (v.x - mu) * inv * g4.x + t4.x;
        xp.y = xv.y + (v.y - mu) * inv * g4.y + t4.y;
        xp.z = xv.z + (v.z - mu) * inv * g4.z + t4.z;
        xp.w = xv.w + (v.w - mu) * inv * g4.w + t4.w;
        *(float4*)(xpre + gn * DD + c4) = xp;
        cs.x += xp.x; cs.y += xp.y; cs.z += xp.z; cs.w += xp.w;
        sq_acc += xp.x * xp.x + xp.y * xp.y + xp.z * xp.z + xp.w * xp.w;
    }
    atomicAdd(&csum_s[c4 + 0], cs.x);
    atomicAdd(&csum_s[c4 + 1], cs.y);
    atomicAdd(&csum_s[c4 + 2], cs.z);
    atomicAdd(&csum_s[c4 + 3], cs.w);
#pragma unroll
    for (int o = 16; o > 0; o >>= 1) sq_acc += __shfl_xor_sync(0xffffffffu, sq_acc, o);
    if (lane == 0) atomicAdd(&csum_s[128], sq_acc);
    __syncthreads();
    if (tid < 128)       atomicAdd(&g_colsum[tid], csum_s[tid]);
    else if (tid == 128) atomicAdd(&g_sumsq[0],    csum_s[128]);
}

// ---------------------------------------------------------------------------
__global__ void rms_kernel(int Nn)
{
    __shared__ float red[128];
    int c = threadIdx.x;
    float m = g_colsum[c] / (float)Nn;
    g_mean[c] = m;
    red[c] = m * m;
    __syncthreads();
    for (int o = 64; o > 0; o >>= 1) {
        if (c < o) red[c] += red[c + o];
        __syncthreads();
    }
    if (c == 0) {
        float ssc = g_sumsq[0] - (float)Nn * red[0];
        float rms = sqrtf(ssc / (float)Nn) + 1e-8f;
        g_invrms[0] = 1.0f / rms;
    }
}

__global__ void finalize_kernel(float* __restrict__ xout, int n4)
{
    int i = blockIdx.x * blockDim.x + threadIdx.x;
    if (i < n4) {
        float4 v = ((const float4*)xout)[i];
        int c = (i * 4) & 127;
        float inv = g_invrms[0];
        v.x = (v.x - g_mean[c])     * inv;
        v.y = (v.y - g_mean[c + 1]) * inv;
        v.z = (v.z - g_mean[c + 2]) * inv;
        v.w = (v.w - g_mean[c + 3]) * inv;
        ((float4*)xout)[i] = v;
    }
}

// ---------------------------------------------------------------------------
extern "C" void kernel_launch(void* const* d_in, const int* in_sizes, int n_in,
                              void* d_out, int out_size)
{
    const float* x   = (const float*)d_in[0];
    const float* ea  = (const float*)d_in[1];
    const int*   ei  = (const int*)d_in[2];      // int32 (JAX x64 disabled)
    const float* eW1 = (const float*)d_in[3];
    const float* eb1 = (const float*)d_in[4];
    const float* eW2 = (const float*)d_in[5];
    const float* eb2 = (const float*)d_in[6];
    const float* eg  = (const float*)d_in[7];
    const float* ebt = (const float*)d_in[8];
    const float* nW1 = (const float*)d_in[9];
    const float* nb1 = (const float*)d_in[10];
    const float* nW2 = (const float*)d_in[11];
    const float* nb2 = (const float*)d_in[12];
    const float* ng  = (const float*)d_in[13];
    const float* nbt = (const float*)d_in[14];

    const int Nn = in_sizes[0] / DD;
    const int E  = in_sizes[1] / DD;

    float* xout = (float*)d_out;
    float* eout = xout + (size_t)Nn * DD;

    cudaFuncSetAttribute(edge_kernel, cudaFuncAttributeMaxDynamicSharedMemorySize, SMEM_BYTES);
    cudaFuncSetAttribute(node_kernel, cudaFuncAttributeMaxDynamicSharedMemorySize, SMEM_BYTES);

    void *aggp, *csp, *sqp, *xfp;
    cudaGetSymbolAddress(&aggp, g_agg);
    cudaGetSymbolAddress(&csp,  g_colsum);
    cudaGetSymbolAddress(&sqp,  g_sumsq);
    cudaGetSymbolAddress(&xfp,  g_xf);

    cudaMemsetAsync(aggp, 0, (size_t)Nn * DD * sizeof(float));
    cudaMemsetAsync(csp,  0, DD * sizeof(float));
    cudaMemsetAsync(sqp,  0, sizeof(float));

    {
        int n4 = Nn * DD / 4;
        prep_half<<<(n4 + 255) / 256, 256>>>(x, (__half*)xfp, n4);
        int wtot = 7 * DD * DD / 4;     // all four weight tensors, one launch
        prep_weights<<<(wtot + 255) / 256, 256>>>(eW1, eW2, nW1, nW2);
    }

    const int eblocks = (E + EB - 1) / EB;
    edge_kernel<<<eblocks, NTHR, SMEM_BYTES>>>(ea, ei, eb1, eb2, eg, ebt, eout, E);

    const int nblocks = (Nn + EB - 1) / EB;
    node_kernel<<<nblocks, NTHR, SMEM_BYTES>>>(x, nb1, nb2, ng, nbt, xout, Nn);

    rms_kernel<<<1, 128>>>(Nn);

    const int n4 = Nn * DD / 4;
    finalize_kernel<<<(n4 + 255) / 256, 256>>>(xout, n4);
}